// round 1
// baseline (speedup 1.0000x reference)
#include <cuda_runtime.h>

#define H   4096
#define IN  512
#define OUT 64

// Device-global scratch (no allocations allowed in kernel_launch).
__device__ float g_pre[H];
__device__ float g_x[H];

// ---------------------------------------------------------------------------
// Kernel 0: g_pre[j] = b_i2h[j] + dot(inp, W_i2h[j, :])   (one warp per row j)
// ---------------------------------------------------------------------------
__global__ void k_init_pre(const float* __restrict__ inp,
                           const float* __restrict__ W_i2h,
                           const float* __restrict__ b_i2h) {
    int warp = (blockIdx.x * blockDim.x + threadIdx.x) >> 5;
    int lane = threadIdx.x & 31;
    if (warp >= H) return;
    const float4* wrow = (const float4*)(W_i2h + (size_t)warp * IN);
    const float4* in4  = (const float4*)inp;
    float acc = 0.f;
#pragma unroll
    for (int t = 0; t < (IN / 4) / 32; ++t) {   // 128 float4 per row, 4 iters
        float4 a = wrow[lane + t * 32];
        float4 b = in4 [lane + t * 32];
        acc += a.x * b.x + a.y * b.y + a.z * b.z + a.w * b.w;
    }
#pragma unroll
    for (int o = 16; o; o >>= 1) acc += __shfl_down_sync(0xffffffffu, acc, o);
    if (lane == 0) g_pre[warp] = acc + b_i2h[warp];
}

// ---------------------------------------------------------------------------
// Kernel 1: g_pre[j] += sum_k hidden[k] * (w[k][j] + plas[k][j]*hebb[k][j])
// Each block: 512 columns (128 threads x float4) over a 128-row k-slice.
// Grid: (H/512 = 8) x (32 k-blocks) = 256 blocks. Partials via atomicAdd.
// ---------------------------------------------------------------------------
#define K1_THREADS 128
#define K1_KBLOCKS 32
#define K1_KROWS   (H / K1_KBLOCKS)   // 128

__global__ void __launch_bounds__(K1_THREADS)
k_recur(const float* __restrict__ hidden,
        const float* __restrict__ hebb,
        const float* __restrict__ w,
        const float* __restrict__ plas) {
    int j4 = blockIdx.x * K1_THREADS + threadIdx.x;  // float4 column index
    int k0 = blockIdx.y * K1_KROWS;

    const float4* w4 = (const float4*)w;
    const float4* p4 = (const float4*)plas;
    const float4* h4 = (const float4*)hebb;

    float4 acc = make_float4(0.f, 0.f, 0.f, 0.f);
    size_t base = (size_t)k0 * (H / 4) + j4;
    for (int k = 0; k < K1_KROWS; ++k, base += H / 4) {
        float hk = __ldg(hidden + k0 + k);
        float4 a = w4[base];
        float4 b = p4[base];
        float4 c = h4[base];
        acc.x += hk * fmaf(b.x, c.x, a.x);
        acc.y += hk * fmaf(b.y, c.y, a.y);
        acc.z += hk * fmaf(b.z, c.z, a.z);
        acc.w += hk * fmaf(b.w, c.w, a.w);
    }
    float* pre = g_pre + (size_t)j4 * 4;
    atomicAdd(pre + 0, acc.x);
    atomicAdd(pre + 1, acc.y);
    atomicAdd(pre + 2, acc.z);
    atomicAdd(pre + 3, acc.w);
}

// ---------------------------------------------------------------------------
// Kernel 2: x = relu(pre); store to scratch and to d_out x-region.
// ---------------------------------------------------------------------------
__global__ void k_relu(float* __restrict__ x_out) {
    int j = blockIdx.x * blockDim.x + threadIdx.x;
    if (j >= H) return;
    float v = fmaxf(g_pre[j], 0.f);
    g_x[j]   = v;
    x_out[j] = v;
}

// ---------------------------------------------------------------------------
// Kernel 3: hebb_new[k][j] = (1-learn)*hebb[k][j] + learn*hidden[k]*x[j]
// One float4 per thread. 16.78M elems / 4 = 4.19M threads.
// ---------------------------------------------------------------------------
__global__ void __launch_bounds__(256)
k_hebb(const float* __restrict__ hidden,
       const float* __restrict__ hebb,
       const float* __restrict__ learn_p,
       float* __restrict__ hebb_out) {
    int idx = blockIdx.x * blockDim.x + threadIdx.x;  // float4 index, < 4.19M
    int k   = idx >> 10;        // / (H/4)
    int jc  = idx & 1023;       // % (H/4)
    float learn = __ldg(learn_p);
    float hk    = __ldg(hidden + k);
    float4 hb = ((const float4*)hebb)[idx];
    float4 xv = ((const float4*)g_x)[jc];
    float a = 1.f - learn;
    float s = learn * hk;
    float4 o;
    o.x = fmaf(a, hb.x, s * xv.x);
    o.y = fmaf(a, hb.y, s * xv.y);
    o.z = fmaf(a, hb.z, s * xv.z);
    o.w = fmaf(a, hb.w, s * xv.w);
    ((float4*)hebb_out)[idx] = o;
}

// ---------------------------------------------------------------------------
// Kernel 4: out[o] = tanh(dot(x, W_h2o[o,:]) + b_h2o[o])  (one warp per o)
// ---------------------------------------------------------------------------
__global__ void k_out(const float* __restrict__ W_h2o,
                      const float* __restrict__ b_h2o,
                      float* __restrict__ out) {
    int warp = (blockIdx.x * blockDim.x + threadIdx.x) >> 5;
    int lane = threadIdx.x & 31;
    if (warp >= OUT) return;
    const float4* wr = (const float4*)(W_h2o + (size_t)warp * H);
    const float4* xv = (const float4*)g_x;
    float acc = 0.f;
#pragma unroll
    for (int t = 0; t < (H / 4) / 32; ++t) {  // 1024 float4 per row, 32 iters
        float4 a = wr[lane + t * 32];
        float4 b = xv[lane + t * 32];
        acc += a.x * b.x + a.y * b.y + a.z * b.z + a.w * b.w;
    }
#pragma unroll
    for (int o = 16; o; o >>= 1) acc += __shfl_down_sync(0xffffffffu, acc, o);
    if (lane == 0) out[warp] = tanhf(acc + b_h2o[warp]);
}

// ---------------------------------------------------------------------------
// Input order (metadata): 0 inp, 1 hidden, 2 hebb, 3 W_i2h, 4 b_i2h,
//                         5 w, 6 plas, 7 learn, 8 W_h2o, 9 b_h2o
// Output: [out(64) | x(4096) | hebb_new(16777216)]
// ---------------------------------------------------------------------------
extern "C" void kernel_launch(void* const* d_in, const int* in_sizes, int n_in,
                              void* d_out, int out_size) {
    const float* inp    = (const float*)d_in[0];
    const float* hidden = (const float*)d_in[1];
    const float* hebb   = (const float*)d_in[2];
    const float* W_i2h  = (const float*)d_in[3];
    const float* b_i2h  = (const float*)d_in[4];
    const float* w      = (const float*)d_in[5];
    const float* plas   = (const float*)d_in[6];
    const float* learn  = (const float*)d_in[7];
    const float* W_h2o  = (const float*)d_in[8];
    const float* b_h2o  = (const float*)d_in[9];

    float* out      = (float*)d_out;
    float* x_out    = out + OUT;
    float* hebb_out = out + OUT + H;

    // 0) pre = b + inp @ W_i2h.T   (4096 warps)
    k_init_pre<<<(H * 32 + 255) / 256, 256>>>(inp, W_i2h, b_i2h);

    // 1) pre += hidden @ (w + plas*hebb)
    dim3 g1(H / (K1_THREADS * 4), K1_KBLOCKS);  // (8, 32)
    k_recur<<<g1, K1_THREADS>>>(hidden, hebb, w, plas);

    // 2) x = relu(pre)
    k_relu<<<H / 256, 256>>>(x_out);

    // 3) hebb_new
    int n4 = (H * H) / 4;
    k_hebb<<<n4 / 256, 256>>>(hidden, hebb, learn, hebb_out);

    // 4) out = tanh(x @ W_h2o.T + b)
    k_out<<<(OUT * 32 + 255) / 256, 256>>>(W_h2o, b_h2o, out);
}

// round 2
// speedup vs baseline: 1.7852x; 1.7852x over previous
#include <cuda_runtime.h>

#define H   4096
#define IN  512
#define OUT 64

#define NKB 128            // k-dim split for k_recur
#define KR  (H / NKB)      // 32 rows per k-block

// Device-global scratch (no allocations allowed).
__device__ float g_init[H];                 // bias + i2h term
__device__ float g_part[(size_t)H * NKB];   // [j][kb] partials, 2 MB
__device__ float g_x[H];

// ---------------------------------------------------------------------------
// Kernel 0: g_init[j] = b_i2h[j] + dot(inp, W_i2h[j, :])   (one warp per row)
// ---------------------------------------------------------------------------
__global__ void k_init_pre(const float* __restrict__ inp,
                           const float* __restrict__ W_i2h,
                           const float* __restrict__ b_i2h) {
    int warp = (blockIdx.x * blockDim.x + threadIdx.x) >> 5;
    int lane = threadIdx.x & 31;
    if (warp >= H) return;
    const float4* wrow = (const float4*)(W_i2h + (size_t)warp * IN);
    const float4* in4  = (const float4*)inp;
    float acc = 0.f;
#pragma unroll
    for (int t = 0; t < (IN / 4) / 32; ++t) {
        float4 a = wrow[lane + t * 32];
        float4 b = in4 [lane + t * 32];
        acc += a.x * b.x + a.y * b.y + a.z * b.z + a.w * b.w;
    }
#pragma unroll
    for (int o = 16; o; o >>= 1) acc += __shfl_down_sync(0xffffffffu, acc, o);
    if (lane == 0) g_init[warp] = acc + b_i2h[warp];
}

// ---------------------------------------------------------------------------
// Kernel 1: partial GEMV. Block (bx, kb): columns [bx*1024, +1024) as float4,
// rows [kb*32, +32). 512 blocks x 256 threads = 4096 warps.
// g_part[j][kb] = sum_{k in slice} hidden[k] * (w[k][j] + plas[k][j]*hebb[k][j])
// ---------------------------------------------------------------------------
__global__ void __launch_bounds__(256)
k_recur(const float* __restrict__ hidden,
        const float* __restrict__ hebb,
        const float* __restrict__ w,
        const float* __restrict__ plas) {
    int j4 = blockIdx.x * 256 + threadIdx.x;   // float4 column index, 0..1023
    int kb = blockIdx.y;
    int k0 = kb * KR;

    const float4* w4 = (const float4*)w;
    const float4* p4 = (const float4*)plas;
    const float4* h4 = (const float4*)hebb;

    float4 acc = make_float4(0.f, 0.f, 0.f, 0.f);
    size_t base = (size_t)k0 * (H / 4) + j4;
#pragma unroll 8
    for (int k = 0; k < KR; ++k, base += H / 4) {
        float hk = __ldg(hidden + k0 + k);
        float4 a = w4[base];
        float4 b = p4[base];
        float4 c = h4[base];
        acc.x += hk * fmaf(b.x, c.x, a.x);
        acc.y += hk * fmaf(b.y, c.y, a.y);
        acc.z += hk * fmaf(b.z, c.z, a.z);
        acc.w += hk * fmaf(b.w, c.w, a.w);
    }
    size_t j = (size_t)j4 * 4;
    g_part[(j + 0) * NKB + kb] = acc.x;
    g_part[(j + 1) * NKB + kb] = acc.y;
    g_part[(j + 2) * NKB + kb] = acc.z;
    g_part[(j + 3) * NKB + kb] = acc.w;
}

// ---------------------------------------------------------------------------
// Kernel 2: x[j] = relu(g_init[j] + sum_kb g_part[j][kb]); warp per column.
// ---------------------------------------------------------------------------
__global__ void k_reduce(float* __restrict__ x_out) {
    int warp = (blockIdx.x * blockDim.x + threadIdx.x) >> 5;
    int lane = threadIdx.x & 31;
    if (warp >= H) return;
    const float* p = g_part + (size_t)warp * NKB;
    float s = p[lane] + p[lane + 32] + p[lane + 64] + p[lane + 96];
#pragma unroll
    for (int o = 16; o; o >>= 1) s += __shfl_down_sync(0xffffffffu, s, o);
    if (lane == 0) {
        float v = fmaxf(g_init[warp] + s, 0.f);
        g_x[warp]   = v;
        x_out[warp] = v;
    }
}

// ---------------------------------------------------------------------------
// Kernel 3: hebb_new[k][j] = (1-learn)*hebb[k][j] + learn*hidden[k]*x[j]
// ---------------------------------------------------------------------------
__global__ void __launch_bounds__(256)
k_hebb(const float* __restrict__ hidden,
       const float* __restrict__ hebb,
       const float* __restrict__ learn_p,
       float* __restrict__ hebb_out) {
    int idx = blockIdx.x * blockDim.x + threadIdx.x;  // float4 index
    int k   = idx >> 10;
    int jc  = idx & 1023;
    float learn = __ldg(learn_p);
    float hk    = __ldg(hidden + k);
    float4 hb = ((const float4*)hebb)[idx];
    float4 xv = ((const float4*)g_x)[jc];
    float a = 1.f - learn;
    float s = learn * hk;
    float4 o;
    o.x = fmaf(a, hb.x, s * xv.x);
    o.y = fmaf(a, hb.y, s * xv.y);
    o.z = fmaf(a, hb.z, s * xv.z);
    o.w = fmaf(a, hb.w, s * xv.w);
    ((float4*)hebb_out)[idx] = o;
}

// ---------------------------------------------------------------------------
// Kernel 4: out[o] = tanh(dot(x, W_h2o[o,:]) + b_h2o[o])  (block per output)
// ---------------------------------------------------------------------------
__global__ void __launch_bounds__(256)
k_out(const float* __restrict__ W_h2o,
      const float* __restrict__ b_h2o,
      float* __restrict__ out) {
    int o   = blockIdx.x;
    int tid = threadIdx.x;
    const float4* wr = (const float4*)(W_h2o + (size_t)o * H);
    const float4* xv = (const float4*)g_x;
    float acc = 0.f;
#pragma unroll
    for (int t = 0; t < (H / 4) / 256; ++t) {   // 4 iters
        int idx = tid + t * 256;
        float4 a = wr[idx];
        float4 b = xv[idx];
        acc += a.x * b.x + a.y * b.y + a.z * b.z + a.w * b.w;
    }
#pragma unroll
    for (int s = 16; s; s >>= 1) acc += __shfl_down_sync(0xffffffffu, acc, s);
    __shared__ float red[8];
    if ((tid & 31) == 0) red[tid >> 5] = acc;
    __syncthreads();
    if (tid == 0) {
        float v = red[0] + red[1] + red[2] + red[3] +
                  red[4] + red[5] + red[6] + red[7];
        out[o] = tanhf(v + b_h2o[o]);
    }
}

// ---------------------------------------------------------------------------
// Inputs: 0 inp, 1 hidden, 2 hebb, 3 W_i2h, 4 b_i2h, 5 w, 6 plas,
//         7 learn, 8 W_h2o, 9 b_h2o
// Output: [out(64) | x(4096) | hebb_new(16777216)]
// ---------------------------------------------------------------------------
extern "C" void kernel_launch(void* const* d_in, const int* in_sizes, int n_in,
                              void* d_out, int out_size) {
    const float* inp    = (const float*)d_in[0];
    const float* hidden = (const float*)d_in[1];
    const float* hebb   = (const float*)d_in[2];
    const float* W_i2h  = (const float*)d_in[3];
    const float* b_i2h  = (const float*)d_in[4];
    const float* w      = (const float*)d_in[5];
    const float* plas   = (const float*)d_in[6];
    const float* learn  = (const float*)d_in[7];
    const float* W_h2o  = (const float*)d_in[8];
    const float* b_h2o  = (const float*)d_in[9];

    float* out      = (float*)d_out;
    float* x_out    = out + OUT;
    float* hebb_out = out + OUT + H;

    // 0) g_init = b + inp @ W_i2h.T
    k_init_pre<<<(H * 32 + 255) / 256, 256>>>(inp, W_i2h, b_i2h);

    // 1) partial GEMV over (w + plas*hebb)
    dim3 g1(H / (256 * 4), NKB);   // (4, 128) = 512 blocks
    k_recur<<<g1, 256>>>(hidden, hebb, w, plas);

    // 2) x = relu(init + sum partials)
    k_reduce<<<(H * 32) / 256, 256>>>(x_out);

    // 3) out = tanh(x @ W_h2o.T + b)   (small; launch before the big one
    //    so its latency hides behind k_hebb's tail? stream is serial — order
    //    does not matter, keep logical order)
    k_out<<<OUT, 256>>>(W_h2o, b_h2o, out);

    // 4) hebb_new
    int n4 = (H * H) / 4;
    k_hebb<<<n4 / 256, 256>>>(hidden, hebb, learn, hebb_out);
}

// round 3
// speedup vs baseline: 1.8891x; 1.0582x over previous
#include <cuda_runtime.h>

#define H   4096
#define IN  512
#define OUT 64

#define NKB 128            // k-dim split for k_recur
#define KR  (H / NKB)      // 32 rows per k-block

// Device-global scratch (no allocations allowed).
__device__ float g_part[(size_t)H * NKB];   // [j][kb] partials, 2 MB
__device__ float g_x[H];

// ---------------------------------------------------------------------------
// Kernel 1: partial GEMV. Block (bx, kb): columns [bx*1024, +1024) floats
// (256 threads x float4), rows [kb*32, +32). Grid (4, 128) = 512 blocks.
// g_part[j][kb] = sum_{k in slice} hidden[k] * (w[k][j] + plas[k][j]*hebb[k][j])
// ---------------------------------------------------------------------------
__global__ void __launch_bounds__(256)
k_recur(const float* __restrict__ hidden,
        const float* __restrict__ hebb,
        const float* __restrict__ w,
        const float* __restrict__ plas) {
    int j4 = blockIdx.x * 256 + threadIdx.x;   // float4 column index, 0..1023
    int kb = blockIdx.y;
    int k0 = kb * KR;

    const float4* w4 = (const float4*)w;
    const float4* p4 = (const float4*)plas;
    const float4* h4 = (const float4*)hebb;

    float4 acc = make_float4(0.f, 0.f, 0.f, 0.f);
    size_t base = (size_t)k0 * (H / 4) + j4;
#pragma unroll 8
    for (int k = 0; k < KR; ++k, base += H / 4) {
        float hk = __ldg(hidden + k0 + k);
        float4 a = w4[base];
        float4 b = p4[base];
        float4 c = h4[base];
        acc.x += hk * fmaf(b.x, c.x, a.x);
        acc.y += hk * fmaf(b.y, c.y, a.y);
        acc.z += hk * fmaf(b.z, c.z, a.z);
        acc.w += hk * fmaf(b.w, c.w, a.w);
    }
    size_t j = (size_t)j4 * 4;
    g_part[(j + 0) * NKB + kb] = acc.x;
    g_part[(j + 1) * NKB + kb] = acc.y;
    g_part[(j + 2) * NKB + kb] = acc.z;
    g_part[(j + 3) * NKB + kb] = acc.w;
}

// ---------------------------------------------------------------------------
// Kernel 2 (fused): x[j] = relu( b_i2h[j] + dot(inp, W_i2h[j,:])
//                               + sum_kb g_part[j][kb] )
// One warp per column j. 4096 warps = 512 blocks x 256 threads.
// ---------------------------------------------------------------------------
__global__ void __launch_bounds__(256)
k_reduce(const float* __restrict__ inp,
         const float* __restrict__ W_i2h,
         const float* __restrict__ b_i2h,
         float* __restrict__ x_out) {
    int warp = (blockIdx.x * blockDim.x + threadIdx.x) >> 5;
    int lane = threadIdx.x & 31;
    if (warp >= H) return;

    // recurrent partials (coalesced: 128 floats per row)
    const float* p = g_part + (size_t)warp * NKB;
    float s = p[lane] + p[lane + 32] + p[lane + 64] + p[lane + 96];

    // i2h dot: 512 floats = 128 float4, 4 per lane
    const float4* wrow = (const float4*)(W_i2h + (size_t)warp * IN);
    const float4* in4  = (const float4*)inp;
#pragma unroll
    for (int t = 0; t < (IN / 4) / 32; ++t) {
        float4 a = wrow[lane + t * 32];
        float4 b = in4 [lane + t * 32];
        s += a.x * b.x + a.y * b.y + a.z * b.z + a.w * b.w;
    }
#pragma unroll
    for (int o = 16; o; o >>= 1) s += __shfl_down_sync(0xffffffffu, s, o);
    if (lane == 0) {
        float v = fmaxf(s + b_i2h[warp], 0.f);
        g_x[warp]   = v;
        x_out[warp] = v;
    }
}

// ---------------------------------------------------------------------------
// Kernel 3 (fused): hebb update + output head.
//   hebb_new[k][j] = (1-learn)*hebb[k][j] + learn*hidden[k]*x[j]
// Rows are visited in REVERSED order within each 32-row k-stripe so the
// earliest waves re-read the hebb lines still resident in L2 from k_recur
// (LRU tail = high-r rows of every stripe).
// Blocks 0..63 additionally compute out[o] = tanh(dot(x, W_h2o[o,:]) + b).
// ---------------------------------------------------------------------------
__global__ void __launch_bounds__(256)
k_hebb_out(const float* __restrict__ hidden,
           const float* __restrict__ hebb,
           const float* __restrict__ learn_p,
           const float* __restrict__ W_h2o,
           const float* __restrict__ b_h2o,
           float* __restrict__ hebb_out,
           float* __restrict__ out) {
    __shared__ float red[8];
    int tid = threadIdx.x;

    if (blockIdx.x < OUT) {
        // ---- output head: block o computes out[o] ----
        int o = blockIdx.x;
        const float4* wr = (const float4*)(W_h2o + (size_t)o * H);
        const float4* xv = (const float4*)g_x;
        float acc = 0.f;
#pragma unroll
        for (int t = 0; t < (H / 4) / 256; ++t) {   // 4 iters
            int idx = tid + t * 256;
            float4 a = wr[idx];
            float4 b = xv[idx];
            acc += a.x * b.x + a.y * b.y + a.z * b.z + a.w * b.w;
        }
#pragma unroll
        for (int s = 16; s; s >>= 1) acc += __shfl_down_sync(0xffffffffu, acc, s);
        if ((tid & 31) == 0) red[tid >> 5] = acc;
        __syncthreads();
        if (tid == 0) {
            float v = red[0] + red[1] + red[2] + red[3] +
                      red[4] + red[5] + red[6] + red[7];
            out[o] = tanhf(v + b_h2o[o]);
        }
    }

    // ---- hebb update (all blocks) ----
    int idx = blockIdx.x * 256 + tid;       // float4 index over H*H/4
    int k   = idx >> 10;                    // row
    int jc  = idx & 1023;                   // float4 col
    int krev = (k & ~(KR - 1)) | ((KR - 1) - (k & (KR - 1)));  // reverse in stripe
    size_t e = ((size_t)krev << 10) | jc;

    float learn = __ldg(learn_p);
    float hk    = __ldg(hidden + krev);
    float4 hb = ((const float4*)hebb)[e];
    float4 xv = ((const float4*)g_x)[jc];
    float a = 1.f - learn;
    float s = learn * hk;
    float4 o4;
    o4.x = fmaf(a, hb.x, s * xv.x);
    o4.y = fmaf(a, hb.y, s * xv.y);
    o4.z = fmaf(a, hb.z, s * xv.z);
    o4.w = fmaf(a, hb.w, s * xv.w);
    ((float4*)hebb_out)[e] = o4;
}

// ---------------------------------------------------------------------------
// Inputs: 0 inp, 1 hidden, 2 hebb, 3 W_i2h, 4 b_i2h, 5 w, 6 plas,
//         7 learn, 8 W_h2o, 9 b_h2o
// Output: [out(64) | x(4096) | hebb_new(16777216)]
// ---------------------------------------------------------------------------
extern "C" void kernel_launch(void* const* d_in, const int* in_sizes, int n_in,
                              void* d_out, int out_size) {
    const float* inp    = (const float*)d_in[0];
    const float* hidden = (const float*)d_in[1];
    const float* hebb   = (const float*)d_in[2];
    const float* W_i2h  = (const float*)d_in[3];
    const float* b_i2h  = (const float*)d_in[4];
    const float* w      = (const float*)d_in[5];
    const float* plas   = (const float*)d_in[6];
    const float* learn  = (const float*)d_in[7];
    const float* W_h2o  = (const float*)d_in[8];
    const float* b_h2o  = (const float*)d_in[9];

    float* out      = (float*)d_out;
    float* x_out    = out + OUT;
    float* hebb_out = out + OUT + H;

    // 1) partial GEMV over (w + plas*hebb)
    dim3 g1(H / (256 * 4), NKB);   // (4, 128) = 512 blocks
    k_recur<<<g1, 256>>>(hidden, hebb, w, plas);

    // 2) x = relu(i2h + bias + sum partials)
    k_reduce<<<(H * 32) / 256, 256>>>(inp, W_i2h, b_i2h, x_out);

    // 3) hebb_new + out (fused)
    int n4 = (H * H) / 4;
    k_hebb_out<<<n4 / 256, 256>>>(hidden, hebb, learn, W_h2o, b_h2o,
                                  hebb_out, out);
}